// round 1
// baseline (speedup 1.0000x reference)
#include <cuda_runtime.h>
#include <cuda_bf16.h>

// HONU order-2: out[i] = sum_{j<=k} W[p(j,k)] * x[i,j] * x[i,k] + b
// with p(j,k) = j*64 - j*(j-1)/2 + (k-j)   (combinations_with_replacement order)
//
// Strategy: one thread per row. A expanded to zero-filled upper-triangular
// 64x64 in shared (float4-broadcast reads), x tile staged coalesced into
// padded shared (stride 65 -> conflict-free), row held in registers,
// fully unrolled triangular FMA loop with split accumulators.

#define LDIM 64

__global__ void __launch_bounds__(64, 1) honu_kernel(
    const float* __restrict__ x, const float* __restrict__ W,
    const float* __restrict__ b, float* __restrict__ out)
{
    __shared__ __align__(16) float A[LDIM * LDIM];   // 16 KB
    __shared__ float xs[LDIM * (LDIM + 1)];          // 16.25 KB, padded stride 65

    const int tid  = threadIdx.x;
    const int row0 = blockIdx.x * LDIM;

    // --- Build zero-filled upper-triangular A from packed W (thread tid owns row j=tid)
    {
        const int j   = tid;
        const int off = j * LDIM - (j * (j - 1)) / 2;   // start of row j in packed W
        #pragma unroll 8
        for (int k = 0; k < LDIM; ++k) {
            A[j * LDIM + k] = (k >= j) ? W[off + (k - j)] : 0.0f;
        }
    }

    // --- Stage 64x64 x tile: coalesced float4 global loads, scalar stores to padded smem
    {
        const float4* xg4 = reinterpret_cast<const float4*>(x + (size_t)row0 * LDIM);
        #pragma unroll
        for (int it = 0; it < 16; ++it) {
            int i  = it * 64 + tid;
            int r  = i >> 4;          // row within tile
            int c4 = i & 15;          // float4 column
            float4 v = xg4[r * 16 + c4];
            xs[r * 65 + c4 * 4 + 0] = v.x;
            xs[r * 65 + c4 * 4 + 1] = v.y;
            xs[r * 65 + c4 * 4 + 2] = v.z;
            xs[r * 65 + c4 * 4 + 3] = v.w;
        }
    }
    __syncthreads();

    // --- Pull this thread's row into registers (conflict-free: bank = (tid + c) % 32)
    float xr[LDIM];
    #pragma unroll
    for (int c = 0; c < LDIM; ++c) xr[c] = xs[tid * 65 + c];

    // --- Triangular quadratic form. Inner sums per j use 4 independent chains
    //     (one per float4 lane); outer uses 2 accumulators to break the RAW chain.
    const float4* A4 = reinterpret_cast<const float4*>(A);
    float acc0 = 0.0f, acc1 = 0.0f;
    #pragma unroll
    for (int j = 0; j < LDIM; ++j) {
        float i0 = 0.0f, i1 = 0.0f, i2 = 0.0f, i3 = 0.0f;
        #pragma unroll
        for (int q = (j >> 2); q < 16; ++q) {
            float4 w = A4[j * 16 + q];           // broadcast LDS.128 (same addr all lanes)
            i0 = fmaf(w.x, xr[4 * q + 0], i0);
            i1 = fmaf(w.y, xr[4 * q + 1], i1);
            i2 = fmaf(w.z, xr[4 * q + 2], i2);
            i3 = fmaf(w.w, xr[4 * q + 3], i3);
        }
        float inner = (i0 + i1) + (i2 + i3);
        if (j & 1) acc1 = fmaf(xr[j], inner, acc1);
        else       acc0 = fmaf(xr[j], inner, acc0);
    }

    out[row0 + tid] = acc0 + acc1 + b[0];
}

extern "C" void kernel_launch(void* const* d_in, const int* in_sizes, int n_in,
                              void* d_out, int out_size) {
    const float* x = (const float*)d_in[0];   // (16384, 64) f32
    const float* W = (const float*)d_in[1];   // (2145,)  f32 (first 2080 used)
    const float* b = (const float*)d_in[2];   // (1,)     f32
    float*     out = (float*)d_out;           // (16384, 1) f32

    const int nrows  = out_size;              // 16384
    const int blocks = (nrows + LDIM - 1) / LDIM;   // 256
    honu_kernel<<<blocks, 64>>>(x, W, b, out);
}